// round 11
// baseline (speedup 1.0000x reference)
#include <cuda_runtime.h>
#include <math.h>
#include <stdint.h>

#define B_  32
#define N_  1024
#define D_  256
#define NEGMASK (-9.0e15f)
#define ALPHA_  0.2f

// ---------------- device scratch ----------------
__device__ float g_z [B_ * N_ * D_];     // z  [b][j][d]
__device__ float g_zt[B_ * N_ * D_];     // zt [b][d][j]  (tf32-rounded)
__device__ float g_s1[B_ * N_];
__device__ float g_s2[B_ * N_];
__device__ float g_m [B_ * N_];
__device__ float g_linv[B_ * N_];
__device__ unsigned g_bits[B_ * N_ * 32];

// ---------------- helpers ----------------
__device__ __forceinline__ uint32_t smem_u32(const void* p) {
    uint32_t a;
    asm("{ .reg .u64 t; cvta.to.shared.u64 t, %1; cvt.u32.u64 %0, t; }" : "=r"(a) : "l"(p));
    return a;
}
__device__ __forceinline__ uint32_t tf32u(float f) {
    uint32_t u; asm("cvt.rna.tf32.f32 %0, %1;" : "=r"(u) : "f"(f));
    return u;
}
__device__ __forceinline__ float tf32f(float f) { return __uint_as_float(tf32u(f)); }

#define CP_ASYNC16(sm, gp) \
    asm volatile("cp.async.cg.shared.global [%0], [%1], 16;" :: "r"(sm), "l"(gp) : "memory")
#define CP_COMMIT()  asm volatile("cp.async.commit_group;" ::: "memory")
#define CP_WAIT0()   asm volatile("cp.async.wait_group 0;" ::: "memory")

__device__ __forceinline__ void mma_tf32(float* c, uint32_t a0, uint32_t a1,
                                         uint32_t a2, uint32_t a3,
                                         uint32_t b0, uint32_t b1) {
    asm volatile(
        "mma.sync.aligned.m16n8k8.row.col.f32.tf32.tf32.f32 "
        "{%0,%1,%2,%3}, {%4,%5,%6,%7}, {%8,%9}, {%0,%1,%2,%3};"
        : "+f"(c[0]), "+f"(c[1]), "+f"(c[2]), "+f"(c[3])
        : "r"(a0), "r"(a1), "r"(a2), "r"(a3), "r"(b0), "r"(b1));
}

// ---------------------------------------------------------------------------
// Kernel 1: z = h @ W^T + b   (fp32 FFMA GEMM -- proven, 127us)
// ---------------------------------------------------------------------------
__global__ __launch_bounds__(256) void k_zgemm(const float* __restrict__ h,
                                               const float* __restrict__ W,
                                               const float* __restrict__ bias) {
    __shared__ float As[8][128];
    __shared__ float Bs[8][128];
    const int t  = threadIdx.x;
    const int bm = blockIdx.y;
    const int bn = blockIdx.x;
    const int tr = t >> 4, tc = t & 15;
    const int lm = t >> 1, lx = t & 1;

    const float* hA = h + (size_t)(bm * 128 + lm) * D_ + 4 * lx;
    const float* wB = W + (size_t)(bn * 128 + lm) * D_ + 4 * lx;

    float acc[8][8];
#pragma unroll
    for (int i = 0; i < 8; i++)
#pragma unroll
        for (int j = 0; j < 8; j++) acc[i][j] = 0.f;

    for (int k0 = 0; k0 < D_; k0 += 8) {
        float4 av = *(const float4*)(hA + k0);
        float4 bv = *(const float4*)(wB + k0);
        As[4 * lx + 0][lm] = av.x; As[4 * lx + 1][lm] = av.y;
        As[4 * lx + 2][lm] = av.z; As[4 * lx + 3][lm] = av.w;
        Bs[4 * lx + 0][lm] = bv.x; Bs[4 * lx + 1][lm] = bv.y;
        Bs[4 * lx + 2][lm] = bv.z; Bs[4 * lx + 3][lm] = bv.w;
        __syncthreads();
#pragma unroll
        for (int k = 0; k < 8; k++) {
            float ra[8], rb[8];
            *(float4*)&ra[0] = *(const float4*)&As[k][4 * tr];
            *(float4*)&ra[4] = *(const float4*)&As[k][64 + 4 * tr];
            *(float4*)&rb[0] = *(const float4*)&Bs[k][4 * tc];
            *(float4*)&rb[4] = *(const float4*)&Bs[k][64 + 4 * tc];
#pragma unroll
            for (int i = 0; i < 8; i++)
#pragma unroll
                for (int j = 0; j < 8; j++) acc[i][j] += ra[i] * rb[j];
        }
        __syncthreads();
    }

    float bcol[8];
#pragma unroll
    for (int j = 0; j < 4; j++) {
        bcol[j]     = bias[bn * 128 + 4 * tc + j];
        bcol[4 + j] = bias[bn * 128 + 64 + 4 * tc + j];
    }
#pragma unroll
    for (int i = 0; i < 8; i++) {
        int r   = (i < 4) ? (4 * tr + i) : (64 + 4 * tr + (i - 4));
        int row = bm * 128 + r;
        float* zp = g_z + (size_t)row * D_ + bn * 128;
        float4 o0 = make_float4(acc[i][0] + bcol[0], acc[i][1] + bcol[1],
                                acc[i][2] + bcol[2], acc[i][3] + bcol[3]);
        float4 o1 = make_float4(acc[i][4] + bcol[4], acc[i][5] + bcol[5],
                                acc[i][6] + bcol[6], acc[i][7] + bcol[7]);
        *(float4*)(zp + 4 * tc)      = o0;
        *(float4*)(zp + 64 + 4 * tc) = o1;
    }
}

// ---------------------------------------------------------------------------
// Kernel 2: s1 = z . a1, s2 = z . a2 (proven)
// ---------------------------------------------------------------------------
__global__ __launch_bounds__(128) void k_scores(const float* __restrict__ a) {
    int idx  = blockIdx.x * blockDim.x + threadIdx.x;
    int row  = idx >> 5;
    int lane = idx & 31;
    const float* zr = g_z + (size_t)row * D_;
    float a1 = 0.f, a2 = 0.f;
#pragma unroll
    for (int x = 0; x < 8; x++) {
        int d = lane + 32 * x;
        float v = zr[d];
        a1 += v * __ldg(a + d);
        a2 += v * __ldg(a + D_ + d);
    }
#pragma unroll
    for (int o = 16; o > 0; o >>= 1) {
        a1 += __shfl_xor_sync(0xffffffffu, a1, o);
        a2 += __shfl_xor_sync(0xffffffffu, a2, o);
    }
    if (lane == 0) { g_s1[row] = a1; g_s2[row] = a2; }
}

// ---------------------------------------------------------------------------
// Kernel 3: transpose z -> zt[b][d][j], tf32 (proven R4 plain layout)
// ---------------------------------------------------------------------------
__global__ __launch_bounds__(256) void k_transpose() {
    __shared__ float tile[32][33];
    int b = blockIdx.z, j0 = blockIdx.x << 5, d0 = blockIdx.y << 5;
    int tx = threadIdx.x & 31, ty = threadIdx.x >> 5;
    const float* zb = g_z + ((size_t)b << 18);
#pragma unroll
    for (int q = 0; q < 4; q++)
        tile[ty + 8 * q][tx] = zb[(size_t)(j0 + ty + 8 * q) * D_ + d0 + tx];
    __syncthreads();
    float* zt = g_zt + ((size_t)b << 18);
#pragma unroll
    for (int q = 0; q < 4; q++)
        zt[(size_t)(d0 + ty + 8 * q) * N_ + j0 + tx] =
            tf32f(tile[tx][ty + 8 * q]);
}

// ---------------------------------------------------------------------------
// Kernel 4: per-row mask stats (proven, 44.9us)
// ---------------------------------------------------------------------------
__global__ __launch_bounds__(256) void k_maskstat2(const int* __restrict__ adj) {
    __shared__ float s2s[N_];
    int row0 = blockIdx.x * 8;
    int b    = row0 >> 10;
    {
        const float4* s = (const float4*)(g_s2 + ((size_t)b << 10));
        ((float4*)s2s)[threadIdx.x] = s[threadIdx.x];
    }
    __syncthreads();
    int w = threadIdx.x >> 5, lane = threadIdx.x & 31;
    int row = row0 + w;
    float s1i = g_s1[row];
    const int* arow = adj + (size_t)row * N_;
    float m = -INFINITY;
    uint32_t word = 0;
#pragma unroll
    for (int k = 0; k < 32; k++) {
        int j = lane + 32 * k;
        bool conn = (arow[j] > 0);
        float x = s1i + s2s[j];
        x = (x >= 0.f) ? x : (ALPHA_ * x);
        uint32_t bal = __ballot_sync(0xffffffffu, conn);
        if (lane == k) word = bal;
        if (conn) m = fmaxf(m, x);
    }
#pragma unroll
    for (int o = 16; o > 0; o >>= 1) m = fmaxf(m, __shfl_xor_sync(0xffffffffu, m, o));
    float l = 0.f;
#pragma unroll
    for (int k = 0; k < 32; k++) {
        uint32_t wk = __shfl_sync(0xffffffffu, word, k);
        if ((wk >> lane) & 1u) {
            float x = s1i + s2s[lane + 32 * k];
            x = (x >= 0.f) ? x : (ALPHA_ * x);
            l += __expf(x - m);
        }
    }
#pragma unroll
    for (int o = 16; o > 0; o >>= 1) l += __shfl_xor_sync(0xffffffffu, l, o);
    g_bits[(size_t)row * 32 + lane] = word;
    if (lane == 0) { g_m[row] = m; g_linv[row] = 1.0f / l; }
}

// ---------------------------------------------------------------------------
// Kernel 5: out = ELU( P @ Z ), 512 threads, full d=256 per CTA,
// PS double-buffered, ONE barrier per chunk. (attn4 + the missing prologue
// __syncthreads that caused R7's NaN.)
// smem floats: ZS0[256][36] ZS1 | PS0[128][36] PS1 | S2[1024]
// ---------------------------------------------------------------------------
#define AT_ZS0 0
#define AT_ZS1 9216
#define AT_PS0 18432
#define AT_PS1 23040
#define AT_S2  27648
#define AT_SMF 28672     // 114688 bytes

__global__ __launch_bounds__(512, 1) void k_attn6(const unsigned* __restrict__ bits,
                                                  float* __restrict__ out) {
    extern __shared__ __align__(16) float sm[];
    const uint32_t sb = smem_u32(sm);
    const uint32_t* smu = (const uint32_t*)sm;

    const int t    = threadIdx.x;
    const int lane = t & 31;
    const int wid  = t >> 5;            // 0..15
    const int wr   = wid & 3;           // rows wr*32..+32
    const int wc   = wid >> 2;          // cols wc*64..+64 (0..3)
    const int g    = lane >> 2;
    const int tq   = lane & 3;

    const int b  = blockIdx.y;
    const int i0 = blockIdx.x * 128;

    ((float2*)(sm + AT_S2))[t] = ((const float2*)(g_s2 + ((size_t)b << 10)))[t];

    const int pi = t >> 2, jq = t & 3;  // P-gen: row pi, 8 j's per thread
    const size_t grow = ((size_t)b << 10) + i0 + pi;
    const float s1i  = g_s1[grow];
    const float mi   = g_m[grow];
    const float linv = g_linv[grow];
    const unsigned* brow = bits + grow * 32;

    const char* ztb = (const char*)(g_zt + ((size_t)b << 18));

    float acc[2][8][4];
#pragma unroll
    for (int mt = 0; mt < 2; mt++)
#pragma unroll
        for (int nt = 0; nt < 8; nt++)
#pragma unroll
            for (int q = 0; q < 4; q++) acc[mt][nt][q] = 0.f;

    // prologue: Z(0) -> ZS0  (idx = t + 512q -> d row idx>>3, seg idx&7)
#pragma unroll
    for (int q = 0; q < 4; q++) {
        int idx = t + 512 * q, r = idx >> 3, s = idx & 7;
        CP_ASYNC16(sb + (AT_ZS0 + r * 36 + s * 4) * 4,
                   ztb + (size_t)r * 4096 + s * 16);
    }
    CP_COMMIT();
    __syncthreads();   // S2 visible to all before P-gen(0)  [R7 NaN fix]

    for (int c = 0; c < 32; c++) {
        // ---- P(c) -> PS[c&1]
        {
            uint32_t word = __ldg(brow + c);
            float* prow = sm + ((c & 1) ? AT_PS1 : AT_PS0) + pi * 36 + jq * 8;
            const float* s2c = sm + AT_S2 + c * 32 + jq * 8;
#pragma unroll
            for (int jj = 0; jj < 8; jj += 2) {
                float x0 = s1i + s2c[jj];
                float x1 = s1i + s2c[jj + 1];
                x0 = (x0 >= 0.f) ? x0 : (ALPHA_ * x0);
                x1 = (x1 >= 0.f) ? x1 : (ALPHA_ * x1);
                int jl = jq * 8 + jj;
                float e0 = ((word >> jl) & 1u) ? x0 : NEGMASK;
                float e1 = ((word >> (jl + 1)) & 1u) ? x1 : NEGMASK;
                float2 p;
                p.x = __uint_as_float(tf32u(__expf(e0 - mi) * linv));
                p.y = __uint_as_float(tf32u(__expf(e1 - mi) * linv));
                *(float2*)(prow + jj) = p;
            }
        }
        CP_WAIT0();          // own Z(c) group done
        __syncthreads();     // all: P(c) + Z(c) visible, mma(c-1) complete
        if (c < 31) {        // prefetch Z(c+1), overlapping mma(c)
            uint32_t zoff = ((c + 1) & 1) ? AT_ZS1 : AT_ZS0;
#pragma unroll
            for (int q = 0; q < 4; q++) {
                int idx = t + 512 * q, r = idx >> 3, s = idx & 7;
                CP_ASYNC16(sb + (zoff + r * 36 + s * 4) * 4,
                           ztb + (size_t)r * 4096 + (size_t)(c + 1) * 128 + s * 16);
            }
            CP_COMMIT();
        }
        // ---- mma(c): proven scalar fragment mapping
        {
            const uint32_t zofs = (c & 1) ? AT_ZS1 : AT_ZS0;
            const uint32_t pofs = (c & 1) ? AT_PS1 : AT_PS0;
            const int nb = wc * 64 + g;
            const int rb = wr * 32 + g;
#pragma unroll
            for (int k0 = 0; k0 < 32; k0 += 8) {
                uint32_t bf[8][2];
#pragma unroll
                for (int nt = 0; nt < 8; nt++) {
                    int base = zofs + (nb + nt * 8) * 36 + k0 + tq;
                    bf[nt][0] = smu[base];
                    bf[nt][1] = smu[base + 4];
                }
#pragma unroll
                for (int mt = 0; mt < 2; mt++) {
                    int ab = pofs + (rb + mt * 16) * 36 + k0 + tq;
                    uint32_t a0 = smu[ab];
                    uint32_t a1 = smu[ab + 8 * 36];
                    uint32_t a2 = smu[ab + 4];
                    uint32_t a3 = smu[ab + 8 * 36 + 4];
#pragma unroll
                    for (int nt = 0; nt < 8; nt++)
                        mma_tf32(acc[mt][nt], a0, a1, a2, a3, bf[nt][0], bf[nt][1]);
                }
            }
        }
    }

    // ---- epilogue: ELU + store
#pragma unroll
    for (int mt = 0; mt < 2; mt++) {
        int row0 = i0 + wr * 32 + mt * 16 + g;
        float* o0 = out + (((size_t)b << 10) + row0) * D_ + wc * 64 + 2 * tq;
        float* o1 = o0 + 8 * D_;
#pragma unroll
        for (int nt = 0; nt < 8; nt++) {
            float v0 = acc[mt][nt][0], v1 = acc[mt][nt][1];
            float v2 = acc[mt][nt][2], v3 = acc[mt][nt][3];
            float2 r0, r1;
            r0.x = (v0 > 0.f) ? v0 : expm1f(v0);
            r0.y = (v1 > 0.f) ? v1 : expm1f(v1);
            r1.x = (v2 > 0.f) ? v2 : expm1f(v2);
            r1.y = (v3 > 0.f) ? v3 : expm1f(v3);
            *(float2*)(o0 + nt * 8) = r0;
            *(float2*)(o1 + nt * 8) = r1;
        }
    }
}

// ---------------------------------------------------------------------------
extern "C" void kernel_launch(void* const* d_in, const int* in_sizes, int n_in,
                              void* d_out, int out_size) {
    const float* h    = (const float*)d_in[0];
    const int*   adj  = (const int*)d_in[1];
    const float* W    = (const float*)d_in[2];
    const float* bias = (const float*)d_in[3];
    const float* a    = (const float*)d_in[4];
    float* out = (float*)d_out;
    (void)in_sizes; (void)n_in; (void)out_size;

    cudaFuncSetAttribute(k_attn6, cudaFuncAttributeMaxDynamicSharedMemorySize,
                         AT_SMF * sizeof(float));

    unsigned* bits_p;
    cudaGetSymbolAddress((void**)&bits_p, g_bits);

    k_zgemm<<<dim3(2, 256), 256>>>(h, W, bias);
    k_scores<<<(B_ * N_) / 4, 128>>>(a);
    k_transpose<<<dim3(32, 8, 32), 256>>>();
    k_maskstat2<<<(B_ * N_) / 8, 256>>>(adj);
    k_attn6<<<dim3(8, 32), 512, AT_SMF * sizeof(float)>>>(bits_p, out);
}

// round 12
// speedup vs baseline: 1.1127x; 1.1127x over previous
#include <cuda_runtime.h>
#include <math.h>
#include <stdint.h>

#define B_  32
#define N_  1024
#define D_  256
#define NEGMASK (-9.0e15f)
#define ALPHA_  0.2f

// ---------------- device scratch ----------------
__device__ float g_z [B_ * N_ * D_];     // z [b][j][d], tf32-RNA-rounded
__device__ float g_s1[B_ * N_];
__device__ float g_s2[B_ * N_];
__device__ float g_m [B_ * N_];
__device__ float g_linv[B_ * N_];
__device__ unsigned g_bits[B_ * N_ * 32];

// ---------------- helpers ----------------
__device__ __forceinline__ uint32_t smem_u32(const void* p) {
    uint32_t a;
    asm("{ .reg .u64 t; cvta.to.shared.u64 t, %1; cvt.u32.u64 %0, t; }" : "=r"(a) : "l"(p));
    return a;
}
__device__ __forceinline__ uint32_t tf32u(float f) {
    uint32_t u; asm("cvt.rna.tf32.f32 %0, %1;" : "=r"(u) : "f"(f));
    return u;
}
__device__ __forceinline__ float tf32f(float f) { return __uint_as_float(tf32u(f)); }

#define CP_ASYNC16(sm, gp) \
    asm volatile("cp.async.cg.shared.global [%0], [%1], 16;" :: "r"(sm), "l"(gp) : "memory")
#define CP_COMMIT()  asm volatile("cp.async.commit_group;" ::: "memory")
#define CP_WAIT0()   asm volatile("cp.async.wait_group 0;" ::: "memory")

__device__ __forceinline__ void mma_tf32(float* c, uint32_t a0, uint32_t a1,
                                         uint32_t a2, uint32_t a3,
                                         uint32_t b0, uint32_t b1) {
    asm volatile(
        "mma.sync.aligned.m16n8k8.row.col.f32.tf32.tf32.f32 "
        "{%0,%1,%2,%3}, {%4,%5,%6,%7}, {%8,%9}, {%0,%1,%2,%3};"
        : "+f"(c[0]), "+f"(c[1]), "+f"(c[2]), "+f"(c[3])
        : "r"(a0), "r"(a1), "r"(a2), "r"(a3), "r"(b0), "r"(b1));
}

// ---------------------------------------------------------------------------
// Kernel 1: z = tf32_rna( h @ W^T + b ).  Proven FFMA GEMM + register
// prefetch (LDG for chunk c+1 issued before FFMA(c), hiding LDG latency).
// ---------------------------------------------------------------------------
__global__ __launch_bounds__(256) void k_zgemm5(const float* __restrict__ h,
                                                const float* __restrict__ W,
                                                const float* __restrict__ bias) {
    __shared__ float As[8][128];
    __shared__ float Bs[8][128];
    const int t  = threadIdx.x;
    const int bm = blockIdx.y;
    const int bn = blockIdx.x;
    const int tr = t >> 4, tc = t & 15;
    const int lm = t >> 1, lx = t & 1;

    const float* hA = h + (size_t)(bm * 128 + lm) * D_ + 4 * lx;
    const float* wB = W + (size_t)(bn * 128 + lm) * D_ + 4 * lx;

    float acc[8][8];
#pragma unroll
    for (int i = 0; i < 8; i++)
#pragma unroll
        for (int j = 0; j < 8; j++) acc[i][j] = 0.f;

    float4 av = *(const float4*)(hA);
    float4 bv = *(const float4*)(wB);

    for (int k0 = 0; k0 < D_; k0 += 8) {
        As[4 * lx + 0][lm] = av.x; As[4 * lx + 1][lm] = av.y;
        As[4 * lx + 2][lm] = av.z; As[4 * lx + 3][lm] = av.w;
        Bs[4 * lx + 0][lm] = bv.x; Bs[4 * lx + 1][lm] = bv.y;
        Bs[4 * lx + 2][lm] = bv.z; Bs[4 * lx + 3][lm] = bv.w;
        __syncthreads();
        if (k0 + 8 < D_) {       // prefetch next chunk; overlaps FFMA below
            av = *(const float4*)(hA + k0 + 8);
            bv = *(const float4*)(wB + k0 + 8);
        }
#pragma unroll
        for (int k = 0; k < 8; k++) {
            float ra[8], rb[8];
            *(float4*)&ra[0] = *(const float4*)&As[k][4 * tr];
            *(float4*)&ra[4] = *(const float4*)&As[k][64 + 4 * tr];
            *(float4*)&rb[0] = *(const float4*)&Bs[k][4 * tc];
            *(float4*)&rb[4] = *(const float4*)&Bs[k][64 + 4 * tc];
#pragma unroll
            for (int i = 0; i < 8; i++)
#pragma unroll
                for (int j = 0; j < 8; j++) acc[i][j] += ra[i] * rb[j];
        }
        __syncthreads();
    }

    float bcol[8];
#pragma unroll
    for (int j = 0; j < 4; j++) {
        bcol[j]     = bias[bn * 128 + 4 * tc + j];
        bcol[4 + j] = bias[bn * 128 + 64 + 4 * tc + j];
    }
#pragma unroll
    for (int i = 0; i < 8; i++) {
        int r   = (i < 4) ? (4 * tr + i) : (64 + 4 * tr + (i - 4));
        int row = bm * 128 + r;
        float* zp = g_z + (size_t)row * D_ + bn * 128;
        float4 o0 = make_float4(tf32f(acc[i][0] + bcol[0]), tf32f(acc[i][1] + bcol[1]),
                                tf32f(acc[i][2] + bcol[2]), tf32f(acc[i][3] + bcol[3]));
        float4 o1 = make_float4(tf32f(acc[i][4] + bcol[4]), tf32f(acc[i][5] + bcol[5]),
                                tf32f(acc[i][6] + bcol[6]), tf32f(acc[i][7] + bcol[7]));
        *(float4*)(zp + 4 * tc)      = o0;
        *(float4*)(zp + 64 + 4 * tc) = o1;
    }
}

// ---------------------------------------------------------------------------
// Kernel 2: s1 = z . a1, s2 = z . a2 (proven)
// ---------------------------------------------------------------------------
__global__ __launch_bounds__(128) void k_scores(const float* __restrict__ a) {
    int idx  = blockIdx.x * blockDim.x + threadIdx.x;
    int row  = idx >> 5;
    int lane = idx & 31;
    const float* zr = g_z + (size_t)row * D_;
    float a1 = 0.f, a2 = 0.f;
#pragma unroll
    for (int x = 0; x < 8; x++) {
        int d = lane + 32 * x;
        float v = zr[d];
        a1 += v * __ldg(a + d);
        a2 += v * __ldg(a + D_ + d);
    }
#pragma unroll
    for (int o = 16; o > 0; o >>= 1) {
        a1 += __shfl_xor_sync(0xffffffffu, a1, o);
        a2 += __shfl_xor_sync(0xffffffffu, a2, o);
    }
    if (lane == 0) { g_s1[row] = a1; g_s2[row] = a2; }
}

// ---------------------------------------------------------------------------
// Kernel 3: per-row mask stats (proven, 44.9us)
// ---------------------------------------------------------------------------
__global__ __launch_bounds__(256) void k_maskstat2(const int* __restrict__ adj) {
    __shared__ float s2s[N_];
    int row0 = blockIdx.x * 8;
    int b    = row0 >> 10;
    {
        const float4* s = (const float4*)(g_s2 + ((size_t)b << 10));
        ((float4*)s2s)[threadIdx.x] = s[threadIdx.x];
    }
    __syncthreads();
    int w = threadIdx.x >> 5, lane = threadIdx.x & 31;
    int row = row0 + w;
    float s1i = g_s1[row];
    const int* arow = adj + (size_t)row * N_;
    float m = -INFINITY;
    uint32_t word = 0;
#pragma unroll
    for (int k = 0; k < 32; k++) {
        int j = lane + 32 * k;
        bool conn = (arow[j] > 0);
        float x = s1i + s2s[j];
        x = (x >= 0.f) ? x : (ALPHA_ * x);
        uint32_t bal = __ballot_sync(0xffffffffu, conn);
        if (lane == k) word = bal;
        if (conn) m = fmaxf(m, x);
    }
#pragma unroll
    for (int o = 16; o > 0; o >>= 1) m = fmaxf(m, __shfl_xor_sync(0xffffffffu, m, o));
    float l = 0.f;
#pragma unroll
    for (int k = 0; k < 32; k++) {
        uint32_t wk = __shfl_sync(0xffffffffu, word, k);
        if ((wk >> lane) & 1u) {
            float x = s1i + s2s[lane + 32 * k];
            x = (x >= 0.f) ? x : (ALPHA_ * x);
            l += __expf(x - m);
        }
    }
#pragma unroll
    for (int o = 16; o > 0; o >>= 1) l += __shfl_xor_sync(0xffffffffu, l, o);
    g_bits[(size_t)row * 32 + lane] = word;
    if (lane == 0) { g_m[row] = m; g_linv[row] = 1.0f / l; }
}

// ---------------------------------------------------------------------------
// Kernel 4: out = ELU( P @ Z ).  attn6 structure (proven) with Z read
// DIRECTLY from row-major g_z (no transpose): smem z-tile [32 j][264 fl],
// pad-8 => fragment loads conflict-free (bank = 8*tq + g + const).
// smem floats: ZS0[32][264] ZS1 | PS0[128][36] PS1 | S2[1024]
// ---------------------------------------------------------------------------
#define AT_ZS0 0
#define AT_ZS1 8448
#define AT_PS0 16896
#define AT_PS1 21504
#define AT_S2  26112
#define AT_SMF 27136     // 108544 bytes

__global__ __launch_bounds__(512, 1) void k_attn7(const unsigned* __restrict__ bits,
                                                  float* __restrict__ out) {
    extern __shared__ __align__(16) float sm[];
    const uint32_t sb = smem_u32(sm);
    const uint32_t* smu = (const uint32_t*)sm;

    const int t    = threadIdx.x;
    const int lane = t & 31;
    const int wid  = t >> 5;            // 0..15
    const int wr   = wid & 3;           // rows wr*32..+32
    const int wc   = wid >> 2;          // cols wc*64..+64 (0..3)
    const int g    = lane >> 2;
    const int tq   = lane & 3;

    const int b  = blockIdx.y;
    const int i0 = blockIdx.x * 128;

    ((float2*)(sm + AT_S2))[t] = ((const float2*)(g_s2 + ((size_t)b << 10)))[t];

    const int pi = t >> 2, jq = t & 3;  // P-gen: row pi, 8 j's per thread
    const size_t grow = ((size_t)b << 10) + i0 + pi;
    const float s1i  = g_s1[grow];
    const float mi   = g_m[grow];
    const float linv = g_linv[grow];
    const unsigned* brow = bits + grow * 32;

    const char* zbb = (const char*)(g_z + ((size_t)b << 18));

    float acc[2][8][4];
#pragma unroll
    for (int mt = 0; mt < 2; mt++)
#pragma unroll
        for (int nt = 0; nt < 8; nt++)
#pragma unroll
            for (int q = 0; q < 4; q++) acc[mt][nt][q] = 0.f;

    // Z loader: idx = t + 512q -> j-row idx>>6 (0..31), seg idx&63 (16B units)
#pragma unroll
    for (int q = 0; q < 4; q++) {
        int idx = t + 512 * q, r = idx >> 6, s = idx & 63;
        CP_ASYNC16(sb + (AT_ZS0 + r * 264) * 4 + s * 16,
                   zbb + (size_t)r * 1024 + s * 16);
    }
    CP_COMMIT();
    __syncthreads();   // S2 visible to all before P-gen(0)

    for (int c = 0; c < 32; c++) {
        // ---- P(c) -> PS[c&1]
        {
            uint32_t word = __ldg(brow + c);
            float* prow = sm + ((c & 1) ? AT_PS1 : AT_PS0) + pi * 36 + jq * 8;
            const float* s2c = sm + AT_S2 + c * 32 + jq * 8;
#pragma unroll
            for (int jj = 0; jj < 8; jj += 2) {
                float x0 = s1i + s2c[jj];
                float x1 = s1i + s2c[jj + 1];
                x0 = (x0 >= 0.f) ? x0 : (ALPHA_ * x0);
                x1 = (x1 >= 0.f) ? x1 : (ALPHA_ * x1);
                int jl = jq * 8 + jj;
                float e0 = ((word >> jl) & 1u) ? x0 : NEGMASK;
                float e1 = ((word >> (jl + 1)) & 1u) ? x1 : NEGMASK;
                float2 p;
                p.x = __uint_as_float(tf32u(__expf(e0 - mi) * linv));
                p.y = __uint_as_float(tf32u(__expf(e1 - mi) * linv));
                *(float2*)(prow + jj) = p;
            }
        }
        CP_WAIT0();          // own Z(c) stores arrived
        __syncthreads();     // all: P(c) + Z(c) visible, mma(c-1) complete
        if (c < 31) {        // prefetch Z(c+1), overlapping mma(c)
            uint32_t zoff = ((c + 1) & 1) ? AT_ZS1 : AT_ZS0;
#pragma unroll
            for (int q = 0; q < 4; q++) {
                int idx = t + 512 * q, r = idx >> 6, s = idx & 63;
                CP_ASYNC16(sb + (zoff + r * 264) * 4 + s * 16,
                           zbb + (size_t)(32 * (c + 1) + r) * 1024 + s * 16);
            }
            CP_COMMIT();
        }
        // ---- mma(c): B-fragments straight from row-major z tile
        {
            const uint32_t zofs = (c & 1) ? AT_ZS1 : AT_ZS0;
            const uint32_t pofs = (c & 1) ? AT_PS1 : AT_PS0;
            const int nb = wc * 64 + g;
            const int rb = wr * 32 + g;
#pragma unroll
            for (int k0 = 0; k0 < 32; k0 += 8) {
                uint32_t bf[8][2];
                const int zr0 = zofs + (k0 + tq) * 264 + nb;
#pragma unroll
                for (int nt = 0; nt < 8; nt++) {
                    bf[nt][0] = smu[zr0 + nt * 8];              // Z[k0+tq][n]
                    bf[nt][1] = smu[zr0 + 4 * 264 + nt * 8];    // Z[k0+tq+4][n]
                }
#pragma unroll
                for (int mt = 0; mt < 2; mt++) {
                    int ab = pofs + (rb + mt * 16) * 36 + k0 + tq;
                    uint32_t a0 = smu[ab];
                    uint32_t a1 = smu[ab + 8 * 36];
                    uint32_t a2 = smu[ab + 4];
                    uint32_t a3 = smu[ab + 8 * 36 + 4];
#pragma unroll
                    for (int nt = 0; nt < 8; nt++)
                        mma_tf32(acc[mt][nt], a0, a1, a2, a3, bf[nt][0], bf[nt][1]);
                }
            }
        }
    }

    // ---- epilogue: ELU + store
#pragma unroll
    for (int mt = 0; mt < 2; mt++) {
        int row0 = i0 + wr * 32 + mt * 16 + g;
        float* o0 = out + (((size_t)b << 10) + row0) * D_ + wc * 64 + 2 * tq;
        float* o1 = o0 + 8 * D_;
#pragma unroll
        for (int nt = 0; nt < 8; nt++) {
            float v0 = acc[mt][nt][0], v1 = acc[mt][nt][1];
            float v2 = acc[mt][nt][2], v3 = acc[mt][nt][3];
            float2 r0, r1;
            r0.x = (v0 > 0.f) ? v0 : expm1f(v0);
            r0.y = (v1 > 0.f) ? v1 : expm1f(v1);
            r1.x = (v2 > 0.f) ? v2 : expm1f(v2);
            r1.y = (v3 > 0.f) ? v3 : expm1f(v3);
            *(float2*)(o0 + nt * 8) = r0;
            *(float2*)(o1 + nt * 8) = r1;
        }
    }
}

// ---------------------------------------------------------------------------
extern "C" void kernel_launch(void* const* d_in, const int* in_sizes, int n_in,
                              void* d_out, int out_size) {
    const float* h    = (const float*)d_in[0];
    const int*   adj  = (const int*)d_in[1];
    const float* W    = (const float*)d_in[2];
    const float* bias = (const float*)d_in[3];
    const float* a    = (const float*)d_in[4];
    float* out = (float*)d_out;
    (void)in_sizes; (void)n_in; (void)out_size;

    cudaFuncSetAttribute(k_attn7, cudaFuncAttributeMaxDynamicSharedMemorySize,
                         AT_SMF * sizeof(float));

    unsigned* bits_p;
    cudaGetSymbolAddress((void**)&bits_p, g_bits);

    k_zgemm5<<<dim3(2, 256), 256>>>(h, W, bias);
    k_scores<<<(B_ * N_) / 4, 128>>>(a);
    k_maskstat2<<<(B_ * N_) / 8, 256>>>(adj);
    k_attn7<<<dim3(8, 32), 512, AT_SMF * sizeof(float)>>>(bits_p, out);
}

// round 13
// speedup vs baseline: 1.1275x; 1.0133x over previous
#include <cuda_runtime.h>
#include <math.h>
#include <stdint.h>

#define B_  32
#define N_  1024
#define D_  256
#define NEGMASK (-9.0e15f)
#define ALPHA_  0.2f

// ---------------- device scratch ----------------
__device__ float g_z [B_ * N_ * D_];     // z [b][j][d], tf32-RNA-rounded
__device__ float g_s1[B_ * N_];
__device__ float g_s2[B_ * N_];
__device__ float g_m [B_ * N_];
__device__ float g_linv[B_ * N_];
__device__ unsigned g_bits[B_ * N_ * 32];

// ---------------- helpers ----------------
__device__ __forceinline__ uint32_t smem_u32(const void* p) {
    uint32_t a;
    asm("{ .reg .u64 t; cvta.to.shared.u64 t, %1; cvt.u32.u64 %0, t; }" : "=r"(a) : "l"(p));
    return a;
}
__device__ __forceinline__ uint32_t tf32u(float f) {
    uint32_t u; asm("cvt.rna.tf32.f32 %0, %1;" : "=r"(u) : "f"(f));
    return u;
}
__device__ __forceinline__ float tf32f(float f) { return __uint_as_float(tf32u(f)); }

#define CP_ASYNC16(sm, gp) \
    asm volatile("cp.async.cg.shared.global [%0], [%1], 16;" :: "r"(sm), "l"(gp) : "memory")
#define CP_COMMIT()  asm volatile("cp.async.commit_group;" ::: "memory")
#define CP_WAIT0()   asm volatile("cp.async.wait_group 0;" ::: "memory")

__device__ __forceinline__ void mma_tf32(float* c, uint32_t a0, uint32_t a1,
                                         uint32_t a2, uint32_t a3,
                                         uint32_t b0, uint32_t b1) {
    asm volatile(
        "mma.sync.aligned.m16n8k8.row.col.f32.tf32.tf32.f32 "
        "{%0,%1,%2,%3}, {%4,%5,%6,%7}, {%8,%9}, {%0,%1,%2,%3};"
        : "+f"(c[0]), "+f"(c[1]), "+f"(c[2]), "+f"(c[3])
        : "r"(a0), "r"(a1), "r"(a2), "r"(a3), "r"(b0), "r"(b1));
}

// ---------------------------------------------------------------------------
// Kernel 1: z = tf32_rna( h @ W^T + b )  (proven R12, ~91us)
// ---------------------------------------------------------------------------
__global__ __launch_bounds__(256) void k_zgemm5(const float* __restrict__ h,
                                                const float* __restrict__ W,
                                                const float* __restrict__ bias) {
    __shared__ float As[8][128];
    __shared__ float Bs[8][128];
    const int t  = threadIdx.x;
    const int bm = blockIdx.y;
    const int bn = blockIdx.x;
    const int tr = t >> 4, tc = t & 15;
    const int lm = t >> 1, lx = t & 1;

    const float* hA = h + (size_t)(bm * 128 + lm) * D_ + 4 * lx;
    const float* wB = W + (size_t)(bn * 128 + lm) * D_ + 4 * lx;

    float acc[8][8];
#pragma unroll
    for (int i = 0; i < 8; i++)
#pragma unroll
        for (int j = 0; j < 8; j++) acc[i][j] = 0.f;

    float4 av = *(const float4*)(hA);
    float4 bv = *(const float4*)(wB);

    for (int k0 = 0; k0 < D_; k0 += 8) {
        As[4 * lx + 0][lm] = av.x; As[4 * lx + 1][lm] = av.y;
        As[4 * lx + 2][lm] = av.z; As[4 * lx + 3][lm] = av.w;
        Bs[4 * lx + 0][lm] = bv.x; Bs[4 * lx + 1][lm] = bv.y;
        Bs[4 * lx + 2][lm] = bv.z; Bs[4 * lx + 3][lm] = bv.w;
        __syncthreads();
        if (k0 + 8 < D_) {
            av = *(const float4*)(hA + k0 + 8);
            bv = *(const float4*)(wB + k0 + 8);
        }
#pragma unroll
        for (int k = 0; k < 8; k++) {
            float ra[8], rb[8];
            *(float4*)&ra[0] = *(const float4*)&As[k][4 * tr];
            *(float4*)&ra[4] = *(const float4*)&As[k][64 + 4 * tr];
            *(float4*)&rb[0] = *(const float4*)&Bs[k][4 * tc];
            *(float4*)&rb[4] = *(const float4*)&Bs[k][64 + 4 * tc];
#pragma unroll
            for (int i = 0; i < 8; i++)
#pragma unroll
                for (int j = 0; j < 8; j++) acc[i][j] += ra[i] * rb[j];
        }
        __syncthreads();
    }

    float bcol[8];
#pragma unroll
    for (int j = 0; j < 4; j++) {
        bcol[j]     = bias[bn * 128 + 4 * tc + j];
        bcol[4 + j] = bias[bn * 128 + 64 + 4 * tc + j];
    }
#pragma unroll
    for (int i = 0; i < 8; i++) {
        int r   = (i < 4) ? (4 * tr + i) : (64 + 4 * tr + (i - 4));
        int row = bm * 128 + r;
        float* zp = g_z + (size_t)row * D_ + bn * 128;
        float4 o0 = make_float4(tf32f(acc[i][0] + bcol[0]), tf32f(acc[i][1] + bcol[1]),
                                tf32f(acc[i][2] + bcol[2]), tf32f(acc[i][3] + bcol[3]));
        float4 o1 = make_float4(tf32f(acc[i][4] + bcol[4]), tf32f(acc[i][5] + bcol[5]),
                                tf32f(acc[i][6] + bcol[6]), tf32f(acc[i][7] + bcol[7]));
        *(float4*)(zp + 4 * tc)      = o0;
        *(float4*)(zp + 64 + 4 * tc) = o1;
    }
}

// ---------------------------------------------------------------------------
// Kernel 2: s1 = z . a1, s2 = z . a2 (proven)
// ---------------------------------------------------------------------------
__global__ __launch_bounds__(128) void k_scores(const float* __restrict__ a) {
    int idx  = blockIdx.x * blockDim.x + threadIdx.x;
    int row  = idx >> 5;
    int lane = idx & 31;
    const float* zr = g_z + (size_t)row * D_;
    float a1 = 0.f, a2 = 0.f;
#pragma unroll
    for (int x = 0; x < 8; x++) {
        int d = lane + 32 * x;
        float v = zr[d];
        a1 += v * __ldg(a + d);
        a2 += v * __ldg(a + D_ + d);
    }
#pragma unroll
    for (int o = 16; o > 0; o >>= 1) {
        a1 += __shfl_xor_sync(0xffffffffu, a1, o);
        a2 += __shfl_xor_sync(0xffffffffu, a2, o);
    }
    if (lane == 0) { g_s1[row] = a1; g_s2[row] = a2; }
}

// ---------------------------------------------------------------------------
// Kernel 3: per-row mask stats (proven, 44.9us)
// ---------------------------------------------------------------------------
__global__ __launch_bounds__(256) void k_maskstat2(const int* __restrict__ adj) {
    __shared__ float s2s[N_];
    int row0 = blockIdx.x * 8;
    int b    = row0 >> 10;
    {
        const float4* s = (const float4*)(g_s2 + ((size_t)b << 10));
        ((float4*)s2s)[threadIdx.x] = s[threadIdx.x];
    }
    __syncthreads();
    int w = threadIdx.x >> 5, lane = threadIdx.x & 31;
    int row = row0 + w;
    float s1i = g_s1[row];
    const int* arow = adj + (size_t)row * N_;
    float m = -INFINITY;
    uint32_t word = 0;
#pragma unroll
    for (int k = 0; k < 32; k++) {
        int j = lane + 32 * k;
        bool conn = (arow[j] > 0);
        float x = s1i + s2s[j];
        x = (x >= 0.f) ? x : (ALPHA_ * x);
        uint32_t bal = __ballot_sync(0xffffffffu, conn);
        if (lane == k) word = bal;
        if (conn) m = fmaxf(m, x);
    }
#pragma unroll
    for (int o = 16; o > 0; o >>= 1) m = fmaxf(m, __shfl_xor_sync(0xffffffffu, m, o));
    float l = 0.f;
#pragma unroll
    for (int k = 0; k < 32; k++) {
        uint32_t wk = __shfl_sync(0xffffffffu, word, k);
        if ((wk >> lane) & 1u) {
            float x = s1i + s2s[lane + 32 * k];
            x = (x >= 0.f) ? x : (ALPHA_ * x);
            l += __expf(x - m);
        }
    }
#pragma unroll
    for (int o = 16; o > 0; o >>= 1) l += __shfl_xor_sync(0xffffffffu, l, o);
    g_bits[(size_t)row * 32 + lane] = word;
    if (lane == 0) { g_m[row] = m; g_linv[row] = 1.0f / l; }
}

// ---------------------------------------------------------------------------
// Kernel 4: out = ELU( P @ Z ).  attn7 pipeline (proven), CTA halved to
// 64 i-rows x 256 d with 256 threads -> 2 CTAs/SM: one CTA's mma overlaps
// the other's P-gen/exp/barrier phase.
// smem floats: ZS0[32][264] ZS1 | PS0[64][36] PS1 | S2[1024] = 22528 fl
// ---------------------------------------------------------------------------
#define AT_ZS0 0
#define AT_ZS1 8448
#define AT_PS0 16896
#define AT_PS1 19200
#define AT_S2  21504
#define AT_SMF 22528     // 90112 bytes/CTA, 2 CTAs = 180224 <= 228KB

__global__ __launch_bounds__(256, 2) void k_attn8(const unsigned* __restrict__ bits,
                                                  float* __restrict__ out) {
    extern __shared__ __align__(16) float sm[];
    const uint32_t sb = smem_u32(sm);
    const uint32_t* smu = (const uint32_t*)sm;

    const int t    = threadIdx.x;
    const int lane = t & 31;
    const int wid  = t >> 5;            // 0..7
    const int wr   = wid & 1;           // rows wr*32..+32
    const int wc   = wid >> 1;          // cols wc*64..+64 (0..3)
    const int g    = lane >> 2;
    const int tq   = lane & 3;

    const int b  = blockIdx.y;
    const int i0 = blockIdx.x * 64;

    ((float4*)(sm + AT_S2))[t] = ((const float4*)(g_s2 + ((size_t)b << 10)))[t];

    const int pi = t >> 2, jq = t & 3;  // P-gen: row pi (0..63), 8 j's each
    const size_t grow = ((size_t)b << 10) + i0 + pi;
    const float s1i  = g_s1[grow];
    const float mi   = g_m[grow];
    const float linv = g_linv[grow];
    const unsigned* brow = bits + grow * 32;

    const char* zbb = (const char*)(g_z + ((size_t)b << 18));

    float acc[2][8][4];
#pragma unroll
    for (int mt = 0; mt < 2; mt++)
#pragma unroll
        for (int nt = 0; nt < 8; nt++)
#pragma unroll
            for (int q = 0; q < 4; q++) acc[mt][nt][q] = 0.f;

    // Z loader: 32 rows x 64 segs(16B) = 2048 ops / 256 thr = 8 each
#pragma unroll
    for (int q = 0; q < 8; q++) {
        int idx = t + 256 * q, r = idx >> 6, s = idx & 63;
        CP_ASYNC16(sb + (AT_ZS0 + r * 264) * 4 + s * 16,
                   zbb + (size_t)r * 1024 + s * 16);
    }
    CP_COMMIT();
    __syncthreads();   // S2 visible to all before P-gen(0)

    for (int c = 0; c < 32; c++) {
        // ---- P(c) -> PS[c&1]
        {
            uint32_t word = __ldg(brow + c);
            float* prow = sm + ((c & 1) ? AT_PS1 : AT_PS0) + pi * 36 + jq * 8;
            const float* s2c = sm + AT_S2 + c * 32 + jq * 8;
#pragma unroll
            for (int jj = 0; jj < 8; jj += 2) {
                float x0 = s1i + s2c[jj];
                float x1 = s1i + s2c[jj + 1];
                x0 = (x0 >= 0.f) ? x0 : (ALPHA_ * x0);
                x1 = (x1 >= 0.f) ? x1 : (ALPHA_ * x1);
                int jl = jq * 8 + jj;
                float e0 = ((word >> jl) & 1u) ? x0 : NEGMASK;
                float e1 = ((word >> (jl + 1)) & 1u) ? x1 : NEGMASK;
                float2 p;
                p.x = __uint_as_float(tf32u(__expf(e0 - mi) * linv));
                p.y = __uint_as_float(tf32u(__expf(e1 - mi) * linv));
                *(float2*)(prow + jj) = p;
            }
        }
        CP_WAIT0();          // own Z(c) stores arrived
        __syncthreads();     // all: P(c) + Z(c) visible, mma(c-1) complete
        if (c < 31) {        // prefetch Z(c+1), overlapping mma(c)
            uint32_t zoff = ((c + 1) & 1) ? AT_ZS1 : AT_ZS0;
#pragma unroll
            for (int q = 0; q < 8; q++) {
                int idx = t + 256 * q, r = idx >> 6, s = idx & 63;
                CP_ASYNC16(sb + (zoff + r * 264) * 4 + s * 16,
                           zbb + (size_t)(32 * (c + 1) + r) * 1024 + s * 16);
            }
            CP_COMMIT();
        }
        // ---- mma(c): B-fragments straight from row-major z tile
        {
            const uint32_t zofs = (c & 1) ? AT_ZS1 : AT_ZS0;
            const uint32_t pofs = (c & 1) ? AT_PS1 : AT_PS0;
            const int nb = wc * 64 + g;
            const int rb = wr * 32 + g;
#pragma unroll
            for (int k0 = 0; k0 < 32; k0 += 8) {
                uint32_t bf[8][2];
                const int zr0 = zofs + (k0 + tq) * 264 + nb;
#pragma unroll
                for (int nt = 0; nt < 8; nt++) {
                    bf[nt][0] = smu[zr0 + nt * 8];              // Z[k0+tq][n]
                    bf[nt][1] = smu[zr0 + 4 * 264 + nt * 8];    // Z[k0+tq+4][n]
                }
#pragma unroll
                for (int mt = 0; mt < 2; mt++) {
                    int ab = pofs + (rb + mt * 16) * 36 + k0 + tq;
                    uint32_t a0 = smu[ab];
                    uint32_t a1 = smu[ab + 8 * 36];
                    uint32_t a2 = smu[ab + 4];
                    uint32_t a3 = smu[ab + 8 * 36 + 4];
#pragma unroll
                    for (int nt = 0; nt < 8; nt++)
                        mma_tf32(acc[mt][nt], a0, a1, a2, a3, bf[nt][0], bf[nt][1]);
                }
            }
        }
    }

    // ---- epilogue: ELU + store
#pragma unroll
    for (int mt = 0; mt < 2; mt++) {
        int row0 = i0 + wr * 32 + mt * 16 + g;
        float* o0 = out + (((size_t)b << 10) + row0) * D_ + wc * 64 + 2 * tq;
        float* o1 = o0 + 8 * D_;
#pragma unroll
        for (int nt = 0; nt < 8; nt++) {
            float v0 = acc[mt][nt][0], v1 = acc[mt][nt][1];
            float v2 = acc[mt][nt][2], v3 = acc[mt][nt][3];
            float2 r0, r1;
            r0.x = (v0 > 0.f) ? v0 : expm1f(v0);
            r0.y = (v1 > 0.f) ? v1 : expm1f(v1);
            r1.x = (v2 > 0.f) ? v2 : expm1f(v2);
            r1.y = (v3 > 0.f) ? v3 : expm1f(v3);
            *(float2*)(o0 + nt * 8) = r0;
            *(float2*)(o1 + nt * 8) = r1;
        }
    }
}

// ---------------------------------------------------------------------------
extern "C" void kernel_launch(void* const* d_in, const int* in_sizes, int n_in,
                              void* d_out, int out_size) {
    const float* h    = (const float*)d_in[0];
    const int*   adj  = (const int*)d_in[1];
    const float* W    = (const float*)d_in[2];
    const float* bias = (const float*)d_in[3];
    const float* a    = (const float*)d_in[4];
    float* out = (float*)d_out;
    (void)in_sizes; (void)n_in; (void)out_size;

    cudaFuncSetAttribute(k_attn8, cudaFuncAttributeMaxDynamicSharedMemorySize,
                         AT_SMF * sizeof(float));

    unsigned* bits_p;
    cudaGetSymbolAddress((void**)&bits_p, g_bits);

    k_zgemm5<<<dim3(2, 256), 256>>>(h, W, bias);
    k_scores<<<(B_ * N_) / 4, 128>>>(a);
    k_maskstat2<<<(B_ * N_) / 8, 256>>>(adj);
    k_attn8<<<dim3(16, 32), 256, AT_SMF * sizeof(float)>>>(bits_p, out);
}